// round 12
// baseline (speedup 1.0000x reference)
#include <cuda_runtime.h>
#include <cuda_bf16.h>
#include <cstdint>

#define N_NODES 100000
#define E_EDGES 1600000
#define D 64

#define SCAN_T 256
#define SCAN_ELEMS 2048                 // 8 per thread
#define NB_SCAN ((N_NODES + SCAN_ELEMS - 1) / SCAN_ELEMS)   // 49

typedef unsigned long long ull;

// ---------------- scratch (device globals; no allocation allowed) ----------
__device__ int   g_cnt[N_NODES];
__device__ int   g_off[N_NODES + 1];
__device__ int   g_cursor[N_NODES];
__device__ int   g_src_sorted[E_EDGES];
__device__ int   g_partial[64];
__device__ int   g_is64;                 // 1 if edge_index is int64, 0 if int32
__device__ float g_y[(size_t)N_NODES * D];
__device__ float g_z[(size_t)N_NODES * D];
__device__ float g_h[(size_t)N_NODES * D];

// ---------------- f32x2 packed helpers (Blackwell FFMA2) --------------------
__device__ __forceinline__ void fma2(ull& d, ull a, ull b) {
    asm("fma.rn.f32x2 %0, %1, %2, %0;" : "+l"(d) : "l"(a), "l"(b));
}
__device__ __forceinline__ float2 u2f2(ull v) {
    float2 r;
    asm("mov.b64 {%0, %1}, %2;" : "=f"(r.x), "=f"(r.y) : "l"(v));
    return r;
}

__device__ __forceinline__ int edge_val(const int* ei32, long long idx) {
    if (g_is64) return (int)((const long long*)ei32)[idx];
    return ei32[idx];
}

// ---------------- init: zero counters + dtype probe + constant tail ---------
// int64 indices < 2^31 -> every high word is 0; int32 -> "high words" are
// random indices, nonzero w.h.p.
__global__ void k_init(const int* __restrict__ ei32) {
    int i = blockIdx.x * blockDim.x + threadIdx.x;
    if (i < N_NODES) g_cnt[i] = 0;
    if (i == 0) {
        g_off[N_NODES] = E_EDGES;       // total is a compile-time constant
        int nz_hi = 0;
#pragma unroll 1
        for (int k = 0; k < 64; k++) {
            if (ei32[2 * k + 1] != 0) nz_hi++;
        }
        g_is64 = (nz_hi == 0) ? 1 : 0;
    }
}

// ---------------- CSR build ------------------------------------------------
__global__ void k_hist(const int* __restrict__ ei32) {
    int e = blockIdx.x * blockDim.x + threadIdx.x;
    if (e < E_EDGES) {
        int d = edge_val(ei32, (long long)E_EDGES + e);   // dst
        atomicAdd(&g_cnt[d], 1);
    }
}

__global__ void k_scan1() {
    int base = blockIdx.x * SCAN_ELEMS + threadIdx.x * 8;
    int s = 0;
#pragma unroll
    for (int u = 0; u < 8; u++) {
        int i = base + u;
        if (i < N_NODES) s += g_cnt[i];
    }
    __shared__ int sh[SCAN_T];
    sh[threadIdx.x] = s;
    __syncthreads();
    for (int st = SCAN_T / 2; st > 0; st >>= 1) {
        if (threadIdx.x < st) sh[threadIdx.x] += sh[threadIdx.x + st];
        __syncthreads();
    }
    if (threadIdx.x == 0) g_partial[blockIdx.x] = sh[0];
}

// scan3 with the cross-block prefix (old scan2) computed inline per block:
// each block serially sums g_partial[0..bid) — at most 48 independent LDGs.
__global__ void k_scan3() {
    __shared__ int sh[SCAN_T];
    __shared__ int s_base;
    if (threadIdx.x == 0) {
        int acc = 0;
#pragma unroll 1
        for (int b = 0; b < blockIdx.x; b++) acc += g_partial[b];
        s_base = acc;
    }
    int base = blockIdx.x * SCAN_ELEMS + threadIdx.x * 8;
    int loc[8];
    int s = 0;
#pragma unroll
    for (int u = 0; u < 8; u++) {
        int i = base + u;
        loc[u] = (i < N_NODES) ? g_cnt[i] : 0;
        s += loc[u];
    }
    sh[threadIdx.x] = s;
    __syncthreads();
    for (int st = 1; st < SCAN_T; st <<= 1) {
        int v = 0;
        if (threadIdx.x >= st) v = sh[threadIdx.x - st];
        __syncthreads();
        sh[threadIdx.x] += v;
        __syncthreads();
    }
    int pre = s_base + sh[threadIdx.x] - s;  // exclusive prefix
#pragma unroll
    for (int u = 0; u < 8; u++) {
        int i = base + u;
        if (i < N_NODES) {
            g_off[i] = pre;
            g_cursor[i] = pre;
            pre += loc[u];
        }
    }
}

// ---------------- fused dual GEMM body (packed f32x2 FMA) -------------------
// Y = X @ Wl^T, Z = X @ Wr^T. One thread per node row. K-pair packing:
// a = {x_k, x_{k+1}} free from reading the X row as u64, b = {w[f][k],
// w[f][k+1]} adjacent in row-major W -> pure LDS.128 + FFMA2 inner loop.
__device__ __forceinline__ void gemm_row_f32x2(
    const float* __restrict__ Wsh,     // [64,64] row-major in smem
    const ull* __restrict__ xq,        // 32 packed k-pairs of this row
    float* __restrict__ out)
{
#pragma unroll 1
    for (int f0 = 0; f0 < D; f0 += 8) {
        ull acc[8];
#pragma unroll
        for (int u = 0; u < 8; u++) acc[u] = 0ULL;   // {0.f, 0.f}
#pragma unroll
        for (int k4 = 0; k4 < 16; k4++) {
#pragma unroll
            for (int u = 0; u < 8; u++) {
                ulonglong2 w = *(const ulonglong2*)&Wsh[(f0 + u) * D + k4 * 4];
                fma2(acc[u], xq[2 * k4],     w.x);
                fma2(acc[u], xq[2 * k4 + 1], w.y);
            }
        }
        float o[8];
#pragma unroll
        for (int u = 0; u < 8; u++) {
            float2 p = u2f2(acc[u]);
            o[u] = p.x + p.y;
        }
        *(float4*)&out[f0]     = make_float4(o[0], o[1], o[2], o[3]);
        *(float4*)&out[f0 + 4] = make_float4(o[4], o[5], o[6], o[7]);
    }
}

__device__ __forceinline__ void gemm_dual_body(
    const float* __restrict__ X,
    const float* __restrict__ Wl,
    const float* __restrict__ Wr,
    float* swl, float* swr,
    int row_block_base, int nthreads)
{
    for (int i = threadIdx.x; i < D * D; i += nthreads) {
        swl[i] = Wl[i];
        swr[i] = Wr[i];
    }
    __syncthreads();

    int row = row_block_base + threadIdx.x;
    if (row >= N_NODES) return;

    ull xq[32];
    const ulonglong2* xp = (const ulonglong2*)(X + (size_t)row * D);
#pragma unroll
    for (int i = 0; i < 16; i++) {
        ulonglong2 t = xp[i];
        xq[2 * i]     = t.x;
        xq[2 * i + 1] = t.y;
    }

    gemm_row_f32x2(swl, xq, g_y + (size_t)row * D);
    gemm_row_f32x2(swr, xq, g_z + (size_t)row * D);
}

// ---------------- scatter + gemm0 fused (independent work, one launch) ------
// Blocks [0, NB_E) do the counting-sort scatter; blocks [NB_E, NB_E+NB_G256)
// run the layer-1 dual GEMM. The GEMM needs only x/W1 — independent of CSR —
// so this overlaps it with the sort instead of serializing.
#define NB_E    ((E_EDGES + 255) / 256)     // 6250
#define NB_G256 ((N_NODES + 255) / 256)     // 391

__global__ void __launch_bounds__(256) k_scatter_gemm0(
    const int*   __restrict__ ei32,
    const float* __restrict__ X,
    const float* __restrict__ Wl,
    const float* __restrict__ Wr)
{
    __shared__ float swl[D * D];
    __shared__ float swr[D * D];

    if (blockIdx.x < NB_E) {
        int e = blockIdx.x * 256 + threadIdx.x;
        if (e < E_EDGES) {
            int d = edge_val(ei32, (long long)E_EDGES + e);
            int s = edge_val(ei32, e);
            int p = atomicAdd(&g_cursor[d], 1);
            g_src_sorted[p] = s;
        }
    } else {
        gemm_dual_body(X, Wl, Wr, swl, swr, (int)(blockIdx.x - NB_E) * 256, 256);
    }
}

// Layer-2 GEMM (reads g_h)
__global__ void __launch_bounds__(256) k_gemm1(
    const float* __restrict__ Wl,
    const float* __restrict__ Wr)
{
    __shared__ float swl[D * D];
    __shared__ float swr[D * D];
    gemm_dual_body((const float*)g_h, Wl, Wr, swl, swr, (int)blockIdx.x * 256, 256);
}

// ---------------- gather-mean + combine ------------------------------------
// One warp per node; HALF-warp (16 lanes x float4 = 256B) per gathered row.
// 16-edge unroll -> 8 LDG.128 in flight per lane; avg degree 16 means the
// typical node is one fully-pipelined batch. Cross-half reduce via shfl.xor(16).
template <int LAYER>
__global__ void __launch_bounds__(256) k_agg(
    const float* __restrict__ bias,
    float* __restrict__ OutParam)
{
    int gwarp = (blockIdx.x * blockDim.x + threadIdx.x) >> 5;
    int lane  = threadIdx.x & 31;
    if (gwarp >= N_NODES) return;

    int half = lane >> 4;     // which edge of the pair
    int sub  = lane & 15;     // 16B chunk within the row

    int beg = g_off[gwarp];
    int end = g_off[gwarp + 1];

    const float* Ybase = (const float*)g_y + sub * 4;

    float4 acc = make_float4(0.f, 0.f, 0.f, 0.f);

    for (int j = beg; j < end; j += 32) {
        int idx = (j + lane < end) ? g_src_sorted[j + lane] : 0;
        int m = min(32, end - j);
        int t = 0;
        // 16 edges per iteration: 8 LDG.128 in flight per lane
        for (; t + 16 <= m; t += 16) {
            int s0 = __shfl_sync(0xffffffffu, idx, t      + half);
            int s1 = __shfl_sync(0xffffffffu, idx, t + 2  + half);
            int s2 = __shfl_sync(0xffffffffu, idx, t + 4  + half);
            int s3 = __shfl_sync(0xffffffffu, idx, t + 6  + half);
            int s4 = __shfl_sync(0xffffffffu, idx, t + 8  + half);
            int s5 = __shfl_sync(0xffffffffu, idx, t + 10 + half);
            int s6 = __shfl_sync(0xffffffffu, idx, t + 12 + half);
            int s7 = __shfl_sync(0xffffffffu, idx, t + 14 + half);
            float4 v0 = *(const float4*)(Ybase + (size_t)s0 * D);
            float4 v1 = *(const float4*)(Ybase + (size_t)s1 * D);
            float4 v2 = *(const float4*)(Ybase + (size_t)s2 * D);
            float4 v3 = *(const float4*)(Ybase + (size_t)s3 * D);
            float4 v4 = *(const float4*)(Ybase + (size_t)s4 * D);
            float4 v5 = *(const float4*)(Ybase + (size_t)s5 * D);
            float4 v6 = *(const float4*)(Ybase + (size_t)s6 * D);
            float4 v7 = *(const float4*)(Ybase + (size_t)s7 * D);
            acc.x += ((v0.x + v1.x) + (v2.x + v3.x)) + ((v4.x + v5.x) + (v6.x + v7.x));
            acc.y += ((v0.y + v1.y) + (v2.y + v3.y)) + ((v4.y + v5.y) + (v6.y + v7.y));
            acc.z += ((v0.z + v1.z) + (v2.z + v3.z)) + ((v4.z + v5.z) + (v6.z + v7.z));
            acc.w += ((v0.w + v1.w) + (v2.w + v3.w)) + ((v4.w + v5.w) + (v6.w + v7.w));
        }
        for (; t + 8 <= m; t += 8) {
            int s0 = __shfl_sync(0xffffffffu, idx, t     + half);
            int s1 = __shfl_sync(0xffffffffu, idx, t + 2 + half);
            int s2 = __shfl_sync(0xffffffffu, idx, t + 4 + half);
            int s3 = __shfl_sync(0xffffffffu, idx, t + 6 + half);
            float4 v0 = *(const float4*)(Ybase + (size_t)s0 * D);
            float4 v1 = *(const float4*)(Ybase + (size_t)s1 * D);
            float4 v2 = *(const float4*)(Ybase + (size_t)s2 * D);
            float4 v3 = *(const float4*)(Ybase + (size_t)s3 * D);
            acc.x += (v0.x + v1.x) + (v2.x + v3.x);
            acc.y += (v0.y + v1.y) + (v2.y + v3.y);
            acc.z += (v0.z + v1.z) + (v2.z + v3.z);
            acc.w += (v0.w + v1.w) + (v2.w + v3.w);
        }
        // tail, 2 edges per step (shfl unconditional: full-warp participation)
        for (; t < m; t += 2) {
            int s = __shfl_sync(0xffffffffu, idx, min(t + half, m - 1));
            if (t + half < m) {
                float4 v = *(const float4*)(Ybase + (size_t)s * D);
                acc.x += v.x; acc.y += v.y; acc.z += v.z; acc.w += v.w;
            }
        }
    }

    // combine the two half-warp partial sums
    acc.x += __shfl_xor_sync(0xffffffffu, acc.x, 16);
    acc.y += __shfl_xor_sync(0xffffffffu, acc.y, 16);
    acc.z += __shfl_xor_sync(0xffffffffu, acc.z, 16);
    acc.w += __shfl_xor_sync(0xffffffffu, acc.w, 16);

    if (half == 0) {
        float inv = (end > beg) ? 1.0f / (float)(end - beg) : 0.0f;
        float4 z = *(const float4*)((const float*)g_z + (size_t)gwarp * D + sub * 4);
        float4 b = *(const float4*)(bias + sub * 4);
        float o0 = acc.x * inv + b.x + z.x;
        float o1 = acc.y * inv + b.y + z.y;
        float o2 = acc.z * inv + b.z + z.z;
        float o3 = acc.w * inv + b.w + z.w;
        float* Out = (LAYER == 0) ? (float*)g_h : OutParam;
        if (LAYER == 0) {
            o0 = fmaxf(o0, 0.0f); o1 = fmaxf(o1, 0.0f);
            o2 = fmaxf(o2, 0.0f); o3 = fmaxf(o3, 0.0f);
        }
        *(float4*)(Out + (size_t)gwarp * D + sub * 4) = make_float4(o0, o1, o2, o3);
    }
}

// ---------------- launch ----------------------------------------------------
extern "C" void kernel_launch(void* const* d_in, const int* in_sizes, int n_in,
                              void* d_out, int out_size)
{
    const float* x   = (const float*)d_in[0];
    const int*   ei  = (const int*)d_in[1];     // edge_index (probe handles int32/int64)
    const float* wl1 = (const float*)d_in[2];
    const float* bl1 = (const float*)d_in[3];
    const float* wr1 = (const float*)d_in[4];
    const float* wl2 = (const float*)d_in[5];
    const float* bl2 = (const float*)d_in[6];
    const float* wr2 = (const float*)d_in[7];
    float* out = (float*)d_out;

    const int TB = 256;
    int nbN   = (N_NODES + TB - 1) / TB;        // 391
    int nbAgg = (N_NODES * 32 + TB - 1) / TB;   // 12500

    // CSR build chain (gemm0 overlapped into the scatter launch)
    k_init<<<nbN, TB>>>(ei);
    k_hist<<<NB_E, TB>>>(ei);
    k_scan1<<<NB_SCAN, SCAN_T>>>();
    k_scan3<<<NB_SCAN, SCAN_T>>>();
    k_scatter_gemm0<<<NB_E + NB_G256, TB>>>(ei, x, wl1, wr1);

    // Layer 1 combine: h = relu(mean_agg(y) + b1 + z)
    k_agg<0><<<nbAgg, TB>>>(bl1, nullptr);

    // Layer 2: y = h@wl2^T, z = h@wr2^T ; out = mean_agg(y) + b2 + z
    k_gemm1<<<NB_G256, TB>>>(wl2, wr2);
    k_agg<1><<<nbAgg, TB>>>(bl2, out);
}

// round 13
// speedup vs baseline: 1.1836x; 1.1836x over previous
#include <cuda_runtime.h>
#include <cuda_fp16.h>
#include <cstdint>

#define N_NODES 100000
#define E_EDGES 1600000
#define D 64

#define SCAN_T 256
#define SCAN_ELEMS 2048                 // 8 per thread
#define NB_SCAN ((N_NODES + SCAN_ELEMS - 1) / SCAN_ELEMS)   // 49

typedef unsigned long long ull;

// ---------------- scratch (device globals; no allocation allowed) ----------
__device__ int    g_cnt[N_NODES];
__device__ int    g_off[N_NODES + 1];
__device__ int    g_cursor[N_NODES];
__device__ int    g_src_sorted[E_EDGES];
__device__ int    g_partial[64];
__device__ int    g_is64;                // 1 if edge_index is int64, 0 if int32
__device__ __half g_y[(size_t)N_NODES * D];   // fp16: halves gather traffic
__device__ float  g_z[(size_t)N_NODES * D];
__device__ float  g_h[(size_t)N_NODES * D];

// ---------------- f32x2 packed helpers (Blackwell FFMA2) --------------------
__device__ __forceinline__ void fma2(ull& d, ull a, ull b) {
    asm("fma.rn.f32x2 %0, %1, %2, %0;" : "+l"(d) : "l"(a), "l"(b));
}
__device__ __forceinline__ float2 u2f2(ull v) {
    float2 r;
    asm("mov.b64 {%0, %1}, %2;" : "=f"(r.x), "=f"(r.y) : "l"(v));
    return r;
}

__device__ __forceinline__ int edge_val(const int* ei32, long long idx) {
    if (g_is64) return (int)((const long long*)ei32)[idx];
    return ei32[idx];
}

// ---------------- init: zero counters + dtype probe + constant tail ---------
__global__ void k_init(const int* __restrict__ ei32) {
    int i = blockIdx.x * blockDim.x + threadIdx.x;
    if (i < N_NODES) g_cnt[i] = 0;
    if (i == 0) {
        g_off[N_NODES] = E_EDGES;
        int nz_hi = 0;
#pragma unroll 1
        for (int k = 0; k < 64; k++) {
            if (ei32[2 * k + 1] != 0) nz_hi++;
        }
        g_is64 = (nz_hi == 0) ? 1 : 0;   // int64 high words are all zero
    }
}

// ---------------- CSR build ------------------------------------------------
__global__ void k_hist(const int* __restrict__ ei32) {
    int e = blockIdx.x * blockDim.x + threadIdx.x;
    if (e < E_EDGES) {
        int d = edge_val(ei32, (long long)E_EDGES + e);   // dst
        atomicAdd(&g_cnt[d], 1);
    }
}

__global__ void k_scan1() {
    int base = blockIdx.x * SCAN_ELEMS + threadIdx.x * 8;
    int s = 0;
#pragma unroll
    for (int u = 0; u < 8; u++) {
        int i = base + u;
        if (i < N_NODES) s += g_cnt[i];
    }
    __shared__ int sh[SCAN_T];
    sh[threadIdx.x] = s;
    __syncthreads();
    for (int st = SCAN_T / 2; st > 0; st >>= 1) {
        if (threadIdx.x < st) sh[threadIdx.x] += sh[threadIdx.x + st];
        __syncthreads();
    }
    if (threadIdx.x == 0) g_partial[blockIdx.x] = sh[0];
}

// scan3 with the cross-block prefix computed inline per block (<=48 LDGs).
__global__ void k_scan3() {
    __shared__ int sh[SCAN_T];
    __shared__ int s_base;
    if (threadIdx.x == 0) {
        int acc = 0;
#pragma unroll 1
        for (int b = 0; b < blockIdx.x; b++) acc += g_partial[b];
        s_base = acc;
    }
    int base = blockIdx.x * SCAN_ELEMS + threadIdx.x * 8;
    int loc[8];
    int s = 0;
#pragma unroll
    for (int u = 0; u < 8; u++) {
        int i = base + u;
        loc[u] = (i < N_NODES) ? g_cnt[i] : 0;
        s += loc[u];
    }
    sh[threadIdx.x] = s;
    __syncthreads();
    for (int st = 1; st < SCAN_T; st <<= 1) {
        int v = 0;
        if (threadIdx.x >= st) v = sh[threadIdx.x - st];
        __syncthreads();
        sh[threadIdx.x] += v;
        __syncthreads();
    }
    int pre = s_base + sh[threadIdx.x] - s;  // exclusive prefix
#pragma unroll
    for (int u = 0; u < 8; u++) {
        int i = base + u;
        if (i < N_NODES) {
            g_off[i] = pre;
            g_cursor[i] = pre;
            pre += loc[u];
        }
    }
}

__global__ void k_scatter(const int* __restrict__ ei32) {
    int e = blockIdx.x * blockDim.x + threadIdx.x;
    if (e < E_EDGES) {
        int d = edge_val(ei32, (long long)E_EDGES + e);
        int s = edge_val(ei32, e);
        int p = atomicAdd(&g_cursor[d], 1);
        g_src_sorted[p] = s;
    }
}

// ---------------- fused dual GEMM (packed f32x2 FMA) ------------------------
// Y = X @ Wl^T (fp16 out), Z = X @ Wr^T (fp32 out). One thread per node row.
// K-pair packing: a = {x_k, x_{k+1}} free from reading X row as u64,
// b = {w[f][k], w[f][k+1]} adjacent in row-major W -> LDS.128 + FFMA2 loop.
template <bool HALF_OUT>
__device__ __forceinline__ void gemm_row_f32x2(
    const float* __restrict__ Wsh,
    const ull* __restrict__ xq,
    void* __restrict__ outp, size_t row)
{
#pragma unroll 1
    for (int f0 = 0; f0 < D; f0 += 8) {
        ull acc[8];
#pragma unroll
        for (int u = 0; u < 8; u++) acc[u] = 0ULL;
#pragma unroll
        for (int k4 = 0; k4 < 16; k4++) {
#pragma unroll
            for (int u = 0; u < 8; u++) {
                ulonglong2 w = *(const ulonglong2*)&Wsh[(f0 + u) * D + k4 * 4];
                fma2(acc[u], xq[2 * k4],     w.x);
                fma2(acc[u], xq[2 * k4 + 1], w.y);
            }
        }
        float o[8];
#pragma unroll
        for (int u = 0; u < 8; u++) {
            float2 p = u2f2(acc[u]);
            o[u] = p.x + p.y;
        }
        if (HALF_OUT) {
            __half* out = (__half*)outp + row * D + f0;
            union { uint4 u4; __half2 h[4]; } pk;
            pk.h[0] = __floats2half2_rn(o[0], o[1]);
            pk.h[1] = __floats2half2_rn(o[2], o[3]);
            pk.h[2] = __floats2half2_rn(o[4], o[5]);
            pk.h[3] = __floats2half2_rn(o[6], o[7]);
            *(uint4*)out = pk.u4;
        } else {
            float* out = (float*)outp + row * D + f0;
            *(float4*)&out[0] = make_float4(o[0], o[1], o[2], o[3]);
            *(float4*)&out[4] = make_float4(o[4], o[5], o[6], o[7]);
        }
    }
}

template <int LAYER>
__global__ void __launch_bounds__(128) k_gemm_dual(
    const float* __restrict__ Xin,
    const float* __restrict__ Wl,
    const float* __restrict__ Wr)
{
    __shared__ float swl[D * D];
    __shared__ float swr[D * D];
    for (int i = threadIdx.x; i < D * D; i += 128) {
        swl[i] = Wl[i];
        swr[i] = Wr[i];
    }
    __syncthreads();

    int row = blockIdx.x * 128 + threadIdx.x;
    if (row >= N_NODES) return;

    const float* X = (LAYER == 0) ? Xin : (const float*)g_h;

    ull xq[32];
    const ulonglong2* xp = (const ulonglong2*)(X + (size_t)row * D);
#pragma unroll
    for (int i = 0; i < 16; i++) {
        ulonglong2 t = xp[i];
        xq[2 * i]     = t.x;
        xq[2 * i + 1] = t.y;
    }

    gemm_row_f32x2<true >(swl, xq, (void*)g_y, (size_t)row);
    gemm_row_f32x2<false>(swr, xq, (void*)g_z, (size_t)row);
}

// ---------------- gather-mean + combine ------------------------------------
// One warp per node; HALF-warp (16 lanes x 8B fp16 = 128B) per gathered row.
// 8-edge unroll -> 4 LDG.64 in flight per lane. fp32 accumulation.
__device__ __forceinline__ float4 h4_to_f4(uint2 v) {
    __half2 h0 = *(__half2*)&v.x;
    __half2 h1 = *(__half2*)&v.y;
    float2 f0 = __half22float2(h0);
    float2 f1 = __half22float2(h1);
    return make_float4(f0.x, f0.y, f1.x, f1.y);
}

template <int LAYER>
__global__ void __launch_bounds__(256) k_agg(
    const float* __restrict__ bias,
    float* __restrict__ OutParam)
{
    int gwarp = (blockIdx.x * blockDim.x + threadIdx.x) >> 5;
    int lane  = threadIdx.x & 31;
    if (gwarp >= N_NODES) return;

    int half = lane >> 4;     // which edge of the pair
    int sub  = lane & 15;     // 8B chunk within the 128B fp16 row

    int beg = g_off[gwarp];
    int end = g_off[gwarp + 1];

    const __half* Yh = g_y;

    float4 acc = make_float4(0.f, 0.f, 0.f, 0.f);

    for (int j = beg; j < end; j += 32) {
        int idx = (j + lane < end) ? g_src_sorted[j + lane] : 0;
        int m = min(32, end - j);
        int t = 0;
        // 8 edges per iteration: 4 LDG.64 in flight per lane
        for (; t + 8 <= m; t += 8) {
            int s0 = __shfl_sync(0xffffffffu, idx, t     + half);
            int s1 = __shfl_sync(0xffffffffu, idx, t + 2 + half);
            int s2 = __shfl_sync(0xffffffffu, idx, t + 4 + half);
            int s3 = __shfl_sync(0xffffffffu, idx, t + 6 + half);
            uint2 u0 = *(const uint2*)(Yh + (size_t)s0 * D + sub * 4);
            uint2 u1 = *(const uint2*)(Yh + (size_t)s1 * D + sub * 4);
            uint2 u2 = *(const uint2*)(Yh + (size_t)s2 * D + sub * 4);
            uint2 u3 = *(const uint2*)(Yh + (size_t)s3 * D + sub * 4);
            float4 v0 = h4_to_f4(u0);
            float4 v1 = h4_to_f4(u1);
            float4 v2 = h4_to_f4(u2);
            float4 v3 = h4_to_f4(u3);
            acc.x += (v0.x + v1.x) + (v2.x + v3.x);
            acc.y += (v0.y + v1.y) + (v2.y + v3.y);
            acc.z += (v0.z + v1.z) + (v2.z + v3.z);
            acc.w += (v0.w + v1.w) + (v2.w + v3.w);
        }
        // tail, 2 edges per step (shfl unconditional: full-warp participation)
        for (; t < m; t += 2) {
            int s = __shfl_sync(0xffffffffu, idx, min(t + half, m - 1));
            if (t + half < m) {
                uint2 u = *(const uint2*)(Yh + (size_t)s * D + sub * 4);
                float4 v = h4_to_f4(u);
                acc.x += v.x; acc.y += v.y; acc.z += v.z; acc.w += v.w;
            }
        }
    }

    // combine the two half-warp partial sums
    acc.x += __shfl_xor_sync(0xffffffffu, acc.x, 16);
    acc.y += __shfl_xor_sync(0xffffffffu, acc.y, 16);
    acc.z += __shfl_xor_sync(0xffffffffu, acc.z, 16);
    acc.w += __shfl_xor_sync(0xffffffffu, acc.w, 16);

    if (half == 0) {
        float inv = (end > beg) ? 1.0f / (float)(end - beg) : 0.0f;
        float4 z = *(const float4*)((const float*)g_z + (size_t)gwarp * D + sub * 4);
        float4 b = *(const float4*)(bias + sub * 4);
        float o0 = acc.x * inv + b.x + z.x;
        float o1 = acc.y * inv + b.y + z.y;
        float o2 = acc.z * inv + b.z + z.z;
        float o3 = acc.w * inv + b.w + z.w;
        float* Out = (LAYER == 0) ? (float*)g_h : OutParam;
        if (LAYER == 0) {
            o0 = fmaxf(o0, 0.0f); o1 = fmaxf(o1, 0.0f);
            o2 = fmaxf(o2, 0.0f); o3 = fmaxf(o3, 0.0f);
        }
        *(float4*)(Out + (size_t)gwarp * D + sub * 4) = make_float4(o0, o1, o2, o3);
    }
}

// ---------------- launch ----------------------------------------------------
extern "C" void kernel_launch(void* const* d_in, const int* in_sizes, int n_in,
                              void* d_out, int out_size)
{
    const float* x   = (const float*)d_in[0];
    const int*   ei  = (const int*)d_in[1];     // edge_index (probe handles int32/int64)
    const float* wl1 = (const float*)d_in[2];
    const float* bl1 = (const float*)d_in[3];
    const float* wr1 = (const float*)d_in[4];
    const float* wl2 = (const float*)d_in[5];
    const float* bl2 = (const float*)d_in[6];
    const float* wr2 = (const float*)d_in[7];
    float* out = (float*)d_out;

    const int TB = 256;
    int nbN   = (N_NODES + TB - 1) / TB;        // 391
    int nbE   = (E_EDGES + TB - 1) / TB;        // 6250
    int nbAgg = (N_NODES * 32 + TB - 1) / TB;   // 12500
    int nbG   = (N_NODES + 127) / 128;          // 782

    // CSR build
    k_init<<<nbN, TB>>>(ei);
    k_hist<<<nbE, TB>>>(ei);
    k_scan1<<<NB_SCAN, SCAN_T>>>();
    k_scan3<<<NB_SCAN, SCAN_T>>>();
    k_scatter<<<nbE, TB>>>(ei);

    // Layer 1: y = x@wl1^T (fp16), z = x@wr1^T ; h = relu(mean(y)+b1+z)
    k_gemm_dual<0><<<nbG, 128>>>(x, wl1, wr1);
    k_agg<0><<<nbAgg, TB>>>(bl1, nullptr);

    // Layer 2: y = h@wl2^T (fp16), z = h@wr2^T ; out = mean(y)+b2+z
    k_gemm_dual<1><<<nbG, 128>>>(nullptr, wl2, wr2);
    k_agg<1><<<nbAgg, TB>>>(bl2, out);
}